// round 14
// baseline (speedup 1.0000x reference)
#include <cuda_runtime.h>

#define B_  4
#define N_  16384
#define M_  4096
#define K_  16
#define R2  0.25f
#define NQ  (B_ * M_)
#define LONG_THRESH 4.0f   // |q|^2 above this => long scan, schedule first

// Scratch (device globals; no allocation allowed)
__device__ float4         g_pts[B_ * N_];   // (x, y, z, |p|^2)
__device__ float4         g_n2p[B_ * N_];   // (-2x, -2y, -2z, |p|^2) scan array
__device__ float4         g_ft [B_ * N_];   // (f0, f1, f2, 0) packed feat
__device__ unsigned int   g_qctr, g_front, g_back;
__device__ int            g_qid [NQ];       // pos  -> qid
__device__ float4         g_qpos[NQ];       // pos  -> q  (scan start = 1 load)
__device__ float4         g_qby [NQ];       // qid  -> q  (for MLP)
__device__ unsigned short g_grp [NQ * K_];  // neighbor indices
__device__ int            g_cnt [NQ];       // valid neighbor count

__global__ __launch_bounds__(256) void prep_kernel(const float* __restrict__ xyz,
                                                   const float* __restrict__ feat) {
    int i = blockIdx.x * blockDim.x + threadIdx.x;
    if (i == 0) { g_qctr = 0; g_front = 0; g_back = 0; }   // graph-replay safe
    if (i < B_ * N_) {
        float x = xyz[3 * i + 0];
        float y = xyz[3 * i + 1];
        float z = xyz[3 * i + 2];
        // match jnp.sum(x**2,-1): (x*x + y*y) + z*z, no fma contraction
        float sq = __fadd_rn(__fadd_rn(__fmul_rn(x, x), __fmul_rn(y, y)), __fmul_rn(z, z));
        g_pts[i] = make_float4(x, y, z, sq);
        // -2*coord is exact (power-of-2 scale + sign flip): scan form
        // rn(rn(qw+pw) + dotn) is bit-identical to rn(rn(qw+pw) - rn(2*dot)).
        g_n2p[i] = make_float4(-2.0f * x, -2.0f * y, -2.0f * z, sq);
        g_ft[i]  = make_float4(feat[3 * i + 0], feat[3 * i + 1], feat[3 * i + 2], 0.f);
    }
}

// LPT scheduling: long-scan queries (large |q|^2) first. Also materializes the
// query point per position (pos) and per qid, shortening dependent chains.
__global__ __launch_bounds__(256) void order_kernel(const int* __restrict__ fps_idx) {
    int qid = blockIdx.x * blockDim.x + threadIdx.x;
    if (qid >= NQ) return;
    int b = qid >> 12;
    float4 q = g_pts[(size_t)b * N_ + fps_idx[qid]];
    int pos;
    if (q.w > LONG_THRESH) pos = (int)atomicAdd(&g_front, 1u);
    else                   pos = NQ - 1 - (int)atomicAdd(&g_back, 1u);
    g_qid[pos]  = qid;
    g_qpos[pos] = q;
    g_qby[qid]  = q;
}

// d2 with pre-scaled point: bit-identical to the reference chain (see prep).
__device__ __forceinline__ float d2n(float4 q, float4 n) {
    float dotn = __fadd_rn(__fadd_rn(__fmul_rn(q.x, n.x), __fmul_rn(q.y, n.y)),
                           __fmul_rn(q.z, n.z));
    return __fadd_rn(__fadd_rn(q.w, n.w), dotn);
}

// ---- kernel A: ball query only (no weight registers -> higher occupancy) ----
__global__ __launch_bounds__(256, 5) void ball_kernel() {
    const unsigned FULL = 0xffffffffu;
    int lane = threadIdx.x & 31;

    for (;;) {
        int idx;
        if (lane == 0) idx = (int)atomicAdd(&g_qctr, 1u);
        idx = __shfl_sync(FULL, idx, 0);
        if (idx >= NQ) break;

        float4 q  = g_qpos[idx];
        int   qid = g_qid[idx];
        int   b   = qid >> 12;
        const float4* __restrict__ pl = g_n2p + (size_t)b * N_ + lane;

        int found  = 0;
        int my_idx = 0;               // lane k (k<K_) owns neighbor k
        for (int base = 0; base < N_; base += 256, pl += 256) {
            float4 p0 = pl[0];
            float4 p1 = pl[32];
            float4 p2 = pl[64];
            float4 p3 = pl[96];
            float4 p4 = pl[128];
            float4 p5 = pl[160];
            float4 p6 = pl[192];
            float4 p7 = pl[224];
            unsigned m0 = __ballot_sync(FULL, d2n(q, p0) <= R2);
            unsigned m1 = __ballot_sync(FULL, d2n(q, p1) <= R2);
            unsigned m2 = __ballot_sync(FULL, d2n(q, p2) <= R2);
            unsigned m3 = __ballot_sync(FULL, d2n(q, p3) <= R2);
            unsigned m4 = __ballot_sync(FULL, d2n(q, p4) <= R2);
            unsigned m5 = __ballot_sync(FULL, d2n(q, p5) <= R2);
            unsigned m6 = __ballot_sync(FULL, d2n(q, p6) <= R2);
            unsigned m7 = __ballot_sync(FULL, d2n(q, p7) <= R2);
            unsigned any = (m0 | m1) | (m2 | m3) | ((m4 | m5) | (m6 | m7));
            if (any) {
                // parallel rank-select (ascending group/bit order == serial walk)
                int s0 = __popc(m0);
                int s1 = s0 + __popc(m1);
                int s2 = s1 + __popc(m2);
                int s3 = s2 + __popc(m3);
                int s4 = s3 + __popc(m4);
                int s5 = s4 + __popc(m5);
                int s6 = s5 + __popc(m6);
                int T  = s6 + __popc(m7);
                int r  = lane - found;
                if (r >= 0 && r < T && lane < K_) {
                    unsigned mm; int e, off;
                    if (r < s3) {
                        if (r < s1) {
                            if (r < s0) { mm = m0; e = 0;  off = 0;  }
                            else        { mm = m1; e = s0; off = 32; }
                        } else {
                            if (r < s2) { mm = m2; e = s1; off = 64; }
                            else        { mm = m3; e = s2; off = 96; }
                        }
                    } else {
                        if (r < s5) {
                            if (r < s4) { mm = m4; e = s3; off = 128; }
                            else        { mm = m5; e = s4; off = 160; }
                        } else {
                            if (r < s6) { mm = m6; e = s5; off = 192; }
                            else        { mm = m7; e = s6; off = 224; }
                        }
                    }
                    my_idx = base + off + __fns(mm, 0, (r - e) + 1);
                }
                found += T;
                if (found >= K_) { found = K_; break; }
            }
        }
        // pad missing neighbors with the first valid one (reference semantics)
        int idx0 = __shfl_sync(FULL, my_idx, 0);
        if (lane >= found) my_idx = idx0;

        if (lane < K_) g_grp[qid * K_ + lane] = (unsigned short)my_idx;
        if (lane == 0) g_cnt[qid] = found;
    }
}

// ---- kernel B: MLP + maxpool; one warp per query, uniform dense work ----
__global__ __launch_bounds__(256, 4) void mlp_kernel(
    const float* __restrict__ W1,
    const float* __restrict__ b1,
    const float* __restrict__ W2,
    const float* __restrict__ b2,
    float*       __restrict__ out)
{
    const unsigned FULL = 0xffffffffu;
    int lane = threadIdx.x & 31;
    int qid  = blockIdx.x * 8 + (threadIdx.x >> 5);
    int b    = qid >> 12;

    float w1r[6], w2r[32];
    #pragma unroll
    for (int i = 0; i < 6; i++)  w1r[i] = W1[i * 32 + lane];
    #pragma unroll
    for (int i = 0; i < 32; i++) w2r[i] = W2[i * 32 + lane];
    float b1r = b1[lane];
    float b2r = b2[lane];

    const float4* __restrict__ pts = g_pts + (size_t)b * N_;
    const float4* __restrict__ ftb = g_ft  + (size_t)b * N_;

    float4 q   = g_qby[qid];
    int kmax   = g_cnt[qid];
    int myg    = (lane < K_) ? (int)g_grp[qid * K_ + lane] : 0;

    float acc = -3.402823466e38f;
    #pragma unroll 1
    for (int k = 0; k < kmax; k++) {
        int g = __shfl_sync(FULL, myg, k);
        float4 p = pts[g];                    // broadcast loads (L1/L2 hit)
        float4 f = ftb[g];
        float i0 = p.x - q.x, i1 = p.y - q.y, i2 = p.z - q.z;

        float h1 = b1r;
        h1 += i0  * w1r[0];
        h1 += i1  * w1r[1];
        h1 += i2  * w1r[2];
        h1 += f.x * w1r[3];
        h1 += f.y * w1r[4];
        h1 += f.z * w1r[5];
        h1 = fmaxf(h1, 0.1f * h1);            // leaky relu

        // 4 accumulator chains to break the serial FMA dependency
        float a0 = b2r, a1 = 0.f, a2 = 0.f, a3 = 0.f;
        #pragma unroll
        for (int i = 0; i < 32; i += 4) {
            a0 = fmaf(__shfl_sync(FULL, h1, i + 0), w2r[i + 0], a0);
            a1 = fmaf(__shfl_sync(FULL, h1, i + 1), w2r[i + 1], a1);
            a2 = fmaf(__shfl_sync(FULL, h1, i + 2), w2r[i + 2], a2);
            a3 = fmaf(__shfl_sync(FULL, h1, i + 3), w2r[i + 3], a3);
        }
        float h2 = (a0 + a1) + (a2 + a3);
        h2 = fmaxf(h2, 0.1f * h2);

        acc = fmaxf(acc, h2);
    }

    out[((size_t)qid) * 32 + lane] = acc;
}

extern "C" void kernel_launch(void* const* d_in, const int* in_sizes, int n_in,
                              void* d_out, int out_size) {
    const float* xyz     = (const float*)d_in[0];
    const float* feat    = (const float*)d_in[1];
    const int*   fps_idx = (const int*)  d_in[2];
    const float* W1      = (const float*)d_in[3];
    const float* b1      = (const float*)d_in[4];
    const float* W2      = (const float*)d_in[5];
    const float* b2      = (const float*)d_in[6];
    float* out = (float*)d_out;

    prep_kernel<<<(B_ * N_ + 255) / 256, 256>>>(xyz, feat);
    order_kernel<<<NQ / 256, 256>>>(fps_idx);
    ball_kernel<<<740, 256>>>();                       // persistent, 5 CTAs/SM
    mlp_kernel<<<NQ / 8, 256>>>(W1, b1, W2, b2, out);  // warp per query
    (void)in_sizes; (void)n_in; (void)out_size;
}

// round 15
// speedup vs baseline: 1.3687x; 1.3687x over previous
#include <cuda_runtime.h>

#define B_  4
#define N_  16384
#define M_  4096
#define K_  16
#define R2  0.25f
#define NQ  (B_ * M_)
#define LONG_THRESH 4.0f   // |q|^2 above this => long scan, schedule first

// Scratch (device globals; no allocation allowed)
__device__ float4       g_pts[B_ * N_];   // (x, y, z, |p|^2)
__device__ float4       g_n2p[B_ * N_];   // (-2x, -2y, -2z, |p|^2) scan array
__device__ float4       g_ft [B_ * N_];   // (f0, f1, f2, 0) packed feat
__device__ unsigned int g_qctr, g_front, g_back;
__device__ int          g_qid [NQ];       // pos -> qid
__device__ float4       g_qpos[NQ];       // pos -> q (scan start = 1 load)

__global__ __launch_bounds__(256) void prep_kernel(const float* __restrict__ xyz,
                                                   const float* __restrict__ feat) {
    int i = blockIdx.x * blockDim.x + threadIdx.x;
    if (i == 0) { g_qctr = 0; g_front = 0; g_back = 0; }   // graph-replay safe
    if (i < B_ * N_) {
        float x = xyz[3 * i + 0];
        float y = xyz[3 * i + 1];
        float z = xyz[3 * i + 2];
        // match jnp.sum(x**2,-1): (x*x + y*y) + z*z, no fma contraction
        float sq = __fadd_rn(__fadd_rn(__fmul_rn(x, x), __fmul_rn(y, y)), __fmul_rn(z, z));
        g_pts[i] = make_float4(x, y, z, sq);
        // -2*coord is exact (power-of-2 scale + sign flip): scan form
        // rn(rn(qw+pw) + dotn) is bit-identical to rn(rn(qw+pw) - rn(2*dot)).
        g_n2p[i] = make_float4(-2.0f * x, -2.0f * y, -2.0f * z, sq);
        g_ft[i]  = make_float4(feat[3 * i + 0], feat[3 * i + 1], feat[3 * i + 2], 0.f);
    }
}

// LPT scheduling: long-scan queries (large |q|^2) first. Also materializes the
// query point per position, shortening the scan-start dependent chain.
__global__ __launch_bounds__(256) void order_kernel(const int* __restrict__ fps_idx) {
    int qid = blockIdx.x * blockDim.x + threadIdx.x;
    if (qid >= NQ) return;
    int b = qid >> 12;
    float4 q = g_pts[(size_t)b * N_ + fps_idx[qid]];
    int pos;
    if (q.w > LONG_THRESH) pos = (int)atomicAdd(&g_front, 1u);
    else                   pos = NQ - 1 - (int)atomicAdd(&g_back, 1u);
    g_qid[pos]  = qid;
    g_qpos[pos] = q;
}

// d2 with pre-scaled point: bit-identical to the reference chain (see prep).
__device__ __forceinline__ float d2n(float4 q, float4 n) {
    float dotn = __fadd_rn(__fadd_rn(__fmul_rn(q.x, n.x), __fmul_rn(q.y, n.y)),
                           __fmul_rn(q.z, n.z));
    return __fadd_rn(__fadd_rn(q.w, n.w), dotn);
}

__global__ __launch_bounds__(256, 4) void sa_kernel(
    const float* __restrict__ W1,
    const float* __restrict__ b1,
    const float* __restrict__ W2,
    const float* __restrict__ b2,
    float*       __restrict__ out)
{
    const unsigned FULL = 0xffffffffu;
    int lane = threadIdx.x & 31;

    // hoist this lane's weight columns into registers (inner loops become
    // pure SHFL+FFMA, no LDS/LDG)
    float w1r[6], w2r[32];
    #pragma unroll
    for (int i = 0; i < 6; i++)  w1r[i] = W1[i * 32 + lane];
    #pragma unroll
    for (int i = 0; i < 32; i++) w2r[i] = W2[i * 32 + lane];
    float b1r = b1[lane];
    float b2r = b2[lane];

    // persistent warp: steal one query at a time, longest-first order
    for (;;) {
        int idx;
        if (lane == 0) idx = (int)atomicAdd(&g_qctr, 1u);
        idx = __shfl_sync(FULL, idx, 0);
        if (idx >= NQ) break;

        float4 q  = g_qpos[idx];      // one load; no fps->pts chain
        int   qid = g_qid[idx];
        int   b   = qid >> 12;        // / M_ (4096)
        const float4* __restrict__ pts = g_pts + (size_t)b * N_;
        const float4* __restrict__ pl  = g_n2p + (size_t)b * N_ + lane;

        // ---- ball query: first K_ in-ball indices in ascending order ----
        // 8 independent 16B loads (256 points) in flight before the exit check.
        int found  = 0;
        int my_idx = 0;               // lane k (k<K_) owns neighbor k
        for (int base = 0; base < N_; base += 256, pl += 256) {
            float4 p0 = pl[0];
            float4 p1 = pl[32];
            float4 p2 = pl[64];
            float4 p3 = pl[96];
            float4 p4 = pl[128];
            float4 p5 = pl[160];
            float4 p6 = pl[192];
            float4 p7 = pl[224];
            unsigned m0 = __ballot_sync(FULL, d2n(q, p0) <= R2);
            unsigned m1 = __ballot_sync(FULL, d2n(q, p1) <= R2);
            unsigned m2 = __ballot_sync(FULL, d2n(q, p2) <= R2);
            unsigned m3 = __ballot_sync(FULL, d2n(q, p3) <= R2);
            unsigned m4 = __ballot_sync(FULL, d2n(q, p4) <= R2);
            unsigned m5 = __ballot_sync(FULL, d2n(q, p5) <= R2);
            unsigned m6 = __ballot_sync(FULL, d2n(q, p6) <= R2);
            unsigned m7 = __ballot_sync(FULL, d2n(q, p7) <= R2);
            unsigned any = (m0 | m1) | (m2 | m3) | ((m4 | m5) | (m6 | m7));
            if (any) {
                // parallel rank-select (ascending group/bit order == serial walk)
                int s0 = __popc(m0);
                int s1 = s0 + __popc(m1);
                int s2 = s1 + __popc(m2);
                int s3 = s2 + __popc(m3);
                int s4 = s3 + __popc(m4);
                int s5 = s4 + __popc(m5);
                int s6 = s5 + __popc(m6);
                int T  = s6 + __popc(m7);
                int r  = lane - found;
                if (r >= 0 && r < T && lane < K_) {
                    unsigned mm; int e, off;
                    if (r < s3) {
                        if (r < s1) {
                            if (r < s0) { mm = m0; e = 0;  off = 0;  }
                            else        { mm = m1; e = s0; off = 32; }
                        } else {
                            if (r < s2) { mm = m2; e = s1; off = 64; }
                            else        { mm = m3; e = s2; off = 96; }
                        }
                    } else {
                        if (r < s5) {
                            if (r < s4) { mm = m4; e = s3; off = 128; }
                            else        { mm = m5; e = s4; off = 160; }
                        } else {
                            if (r < s6) { mm = m6; e = s5; off = 192; }
                            else        { mm = m7; e = s6; off = 224; }
                        }
                    }
                    my_idx = base + off + __fns(mm, 0, (r - e) + 1);
                }
                found += T;
                if (found >= K_) { found = K_; break; }
            }
        }
        // pad missing neighbors with the first valid one (reference
        // semantics); found >= 1 always (query is in its own ball).
        int idx0 = __shfl_sync(FULL, my_idx, 0);
        if (lane >= found) my_idx = idx0;
        int kmax = found;                     // padded dups can't change max

        // ---- MLP + maxpool: lane j owns output channel j ----
        const float* __restrict__ ftb = (const float*)(g_ft + (size_t)b * N_);
        float acc = -3.402823466e38f;

        // unroll 2: lets ptxas hoist next iteration's shfl+loads over this
        // iteration's h2 arithmetic. Iteration order & math unchanged.
        #pragma unroll 2
        for (int k = 0; k < kmax; k++) {
            int g = __shfl_sync(FULL, my_idx, k);
            float4 p = pts[g];                       // broadcast load
            float4 f = *(const float4*)(ftb + 4 * g);// packed feat load
            float i0 = p.x - q.x, i1 = p.y - q.y, i2 = p.z - q.z;

            float h1 = b1r;
            h1 += i0  * w1r[0];
            h1 += i1  * w1r[1];
            h1 += i2  * w1r[2];
            h1 += f.x * w1r[3];
            h1 += f.y * w1r[4];
            h1 += f.z * w1r[5];
            h1 = fmaxf(h1, 0.1f * h1);            // leaky relu

            // 4 accumulator chains to break the serial FMA dependency
            float a0 = b2r, a1 = 0.f, a2 = 0.f, a3 = 0.f;
            #pragma unroll
            for (int i = 0; i < 32; i += 4) {
                a0 = fmaf(__shfl_sync(FULL, h1, i + 0), w2r[i + 0], a0);
                a1 = fmaf(__shfl_sync(FULL, h1, i + 1), w2r[i + 1], a1);
                a2 = fmaf(__shfl_sync(FULL, h1, i + 2), w2r[i + 2], a2);
                a3 = fmaf(__shfl_sync(FULL, h1, i + 3), w2r[i + 3], a3);
            }
            float h2 = (a0 + a1) + (a2 + a3);
            h2 = fmaxf(h2, 0.1f * h2);

            acc = fmaxf(acc, h2);
        }

        out[((size_t)qid) * 32 + lane] = acc;
    }
}

extern "C" void kernel_launch(void* const* d_in, const int* in_sizes, int n_in,
                              void* d_out, int out_size) {
    const float* xyz     = (const float*)d_in[0];
    const float* feat    = (const float*)d_in[1];
    const int*   fps_idx = (const int*)  d_in[2];
    const float* W1      = (const float*)d_in[3];
    const float* b1      = (const float*)d_in[4];
    const float* W2      = (const float*)d_in[5];
    const float* b2      = (const float*)d_in[6];
    float* out = (float*)d_out;

    prep_kernel<<<(B_ * N_ + 255) / 256, 256>>>(xyz, feat);
    order_kernel<<<NQ / 256, 256>>>(fps_idx);
    // persistent fused kernel: 4 CTAs/SM, work-stealing queue, longest-first
    sa_kernel<<<592, 256>>>(W1, b1, W2, b2, out);
    (void)in_sizes; (void)n_in; (void)out_size;
}